// round 9
// baseline (speedup 1.0000x reference)
#include <cuda_runtime.h>

// AOLayer: out[b,n,a] = ang * rad, B=512,N=32,A=256,P=6.
// Round 9: r8 retry (compile fix: inline-asm ex2, __exp2f isn't device-side).
// Exact single-wave grid: 148 SMs x 6 blocks/SM (natural regs=40) = 888
// blocks, balanced 18/19-row ranges -> no second-wave straggler tail.
// Hot math identical to r5 (best precision variant).

#define A_DIM 256
#define P_DIM 6
#define BN_DIM (512 * 32)
#define GRID_BLOCKS 888          // 148 SMs * 6 blocks/SM, single wave
#define MAX_ROWS 19              // ceil(16384/888)

__device__ __forceinline__ float ex2f(float x) {
    float r;
    asm("ex2.approx.f32 %0, %1;" : "=f"(r) : "f"(x));
    return r;
}

__global__ void __launch_bounds__(A_DIM) aolayer_kernel(
    const float* __restrict__ pos,      // [BN, 3]
    const float* __restrict__ centers,  // [A, 3]
    const float* __restrict__ exps,     // [A, P]
    const float* __restrict__ coeffs,   // [A, P]
    const int*   __restrict__ powers,   // [A, 3]
    float* __restrict__ out)            // [BN, A]
{
    const int a = threadIdx.x;

    // balanced row range: [bid*16384/888, (bid+1)*16384/888) == *2048/111
    const unsigned bid = blockIdx.x;
    const int row_start = (int)((bid * 2048u) / 111u);
    const int row_end   = (int)(((bid + 1u) * 2048u) / 111u);
    const int nrows     = row_end - row_start;   // 18 or 19

    // ---- per-atom constants (once per block) ----
    const float ncx = -centers[a * 3 + 0];
    const float ncy = -centers[a * 3 + 1];
    const float ncz = -centers[a * 3 + 2];

    const float NEG_LOG2E = -1.4426950408889634f;
    float ep[P_DIM], co[P_DIM];
#pragma unroll
    for (int p = 0; p < P_DIM; p++) {
        ep[p] = exps[a * P_DIM + p] * NEG_LOG2E;
        co[p] = coeffs[a * P_DIM + p];
    }

    const int px = powers[a * 3 + 0];
    const int py = powers[a * 3 + 1];
    const int pz = powers[a * 3 + 2];
    // loop-invariant predicates
    const bool lx = (px >= 1), qx = (px == 2);
    const bool ly = (py >= 1), qy = (py == 2);
    const bool lz = (pz >= 1), qz = (pz == 2);

    // ---- stage this block's pos rows into shared memory ----
    __shared__ float spos[MAX_ROWS * 3];
    if (threadIdx.x < nrows * 3) {
        spos[threadIdx.x] = pos[row_start * 3 + threadIdx.x];
    }
    __syncthreads();

    float* out_base = out + (size_t)row_start * A_DIM + a;

#pragma unroll 4
    for (int r = 0; r < nrows; r++) {
        const float dx = spos[r * 3 + 0] + ncx;
        const float dy = spos[r * 3 + 1] + ncy;
        const float dz = spos[r * 3 + 2] + ncz;

        const float r2 = fmaf(dx, dx, fmaf(dy, dy, dz * dz));

        // radial: dual accumulators, 6 MUFU ex2
        float rad0 = co[0] * ex2f(ep[0] * r2);
        float rad1 = co[1] * ex2f(ep[1] * r2);
        rad0 = fmaf(co[2], ex2f(ep[2] * r2), rad0);
        rad1 = fmaf(co[3], ex2f(ep[3] * r2), rad1);
        rad0 = fmaf(co[4], ex2f(ep[4] * r2), rad0);
        rad1 = fmaf(co[5], ex2f(ep[5] * r2), rad1);

        float o = rad0 + rad1;

        // angular as predicated muls (predicates loop-invariant)
        if (lx) o *= dx;
        if (qx) o *= dx;
        if (ly) o *= dy;
        if (qy) o *= dy;
        if (lz) o *= dz;
        if (qz) o *= dz;

        out_base[r * A_DIM] = o;
    }
}

extern "C" void kernel_launch(void* const* d_in, const int* in_sizes, int n_in,
                              void* d_out, int out_size) {
    const float* pos     = (const float*)d_in[0];
    const float* centers = (const float*)d_in[1];
    const float* exps    = (const float*)d_in[2];
    const float* coeffs  = (const float*)d_in[3];
    const int*   powers  = (const int*)d_in[4];
    float* out = (float*)d_out;

    dim3 grid(GRID_BLOCKS);   // 888 = 148 SMs * 6 blocks, exactly one wave
    dim3 block(A_DIM);        // 256 threads, one per atom
    aolayer_kernel<<<grid, block>>>(pos, centers, exps, coeffs, powers, out);
}